// round 7
// baseline (speedup 1.0000x reference)
#include <cuda_runtime.h>
#include <cstdint>

#define NB 4
#define NP 8192
#define CH 64
#define KNB 16
// 1/sqrt(1 + 1e-5)
#define BN_SC 0.9999950000374997f

// scratch: transposed activations x_t (B, N, C), double-buffered. 8 MB each.
__device__ __align__(16) float g_xt0[NB * NP * CH];
__device__ __align__(16) float g_xt1[NB * NP * CH];

__device__ __forceinline__ unsigned long long pk2(float x, float y) {
    unsigned long long r;
    asm("mov.b64 %0, {%1, %2};" : "=l"(r) : "f"(x), "f"(y));
    return r;
}
__device__ __forceinline__ void fma2(unsigned long long& d, unsigned long long a, unsigned long long b) {
    asm("fma.rn.f32x2 %0, %1, %2, %0;" : "+l"(d) : "l"(a), "l"(b));
}
__device__ __forceinline__ void upk2(unsigned long long v, float& x, float& y) {
    asm("mov.b64 {%0, %1}, %2;" : "=f"(x), "=f"(y) : "l"(v));
}

// Channel-split 64->64 layer. Each lane owns 32 output channels
// ([halfOff, halfOff+32)) and holds 32 input channels of the SAME half in
// in[]. Partner half's inputs are fetched via shfl_xor(16) — one shuffle
// serves both lanes of the column pair. acc must be pre-initialized
// (bias [+ gather]); finalize writes out[32] with optional relu.
template <bool RELU>
__device__ __forceinline__ void layer_half(const float* __restrict__ Wt,
                                           int halfOff, int half,
                                           const float* in,
                                           unsigned long long* acc, float* out) {
#pragma unroll
    for (int i = 0; i < 32; i++) {
        float mine = in[i];
        float theirs = __shfl_xor_sync(0xffffffffu, mine, 16);
        float vLow = half ? theirs : mine;    // global input channel i
        float vHigh = half ? mine : theirs;   // global input channel i+32
        {
            unsigned long long v2 = pk2(vLow, vLow);
            const ulonglong2* wr = reinterpret_cast<const ulonglong2*>(Wt + i * CH + halfOff);
#pragma unroll
            for (int q = 0; q < 8; q++) {
                ulonglong2 w = wr[q];
                fma2(acc[2 * q + 0], w.x, v2);
                fma2(acc[2 * q + 1], w.y, v2);
            }
        }
        {
            unsigned long long v2 = pk2(vHigh, vHigh);
            const ulonglong2* wr = reinterpret_cast<const ulonglong2*>(Wt + (i + 32) * CH + halfOff);
#pragma unroll
            for (int q = 0; q < 8; q++) {
                ulonglong2 w = wr[q];
                fma2(acc[2 * q + 0], w.x, v2);
                fma2(acc[2 * q + 1], w.y, v2);
            }
        }
    }
#pragma unroll
    for (int q = 0; q < 16; q++) {
        float x, y;
        upk2(acc[q], x, y);
        out[2 * q + 0] = RELU ? fmaxf(x, 0.f) : x;
        out[2 * q + 1] = RELU ? fmaxf(y, 0.f) : y;
    }
}

__device__ __forceinline__ void acc_init_bias_half(const float* __restrict__ B, int halfOff,
                                                   unsigned long long* acc) {
#pragma unroll
    for (int q = 0; q < 8; q++) {
        float4 bv = *(const float4*)&B[halfOff + 4 * q];
        acc[2 * q + 0] = pk2(bv.x, bv.y);
        acc[2 * q + 1] = pk2(bv.z, bv.w);
    }
}

// One PointTransformer block. x in/out in TRANSPOSED layout (B, N, C).
// Warp layout: lane = half*16 + kk. One warp handles ONE point:
// 16 neighbors (kk) x 2 channel-halves (half).
__global__ void __launch_bounds__(256, 2)
pt_block_kernel(const float* __restrict__ p,      // (B,3,N)
                const float* __restrict__ xt_in,  // (B,N,C)
                const int* __restrict__ idx,      // (B,N,K)
                const float* __restrict__ dw1, const float* __restrict__ db1,
                const float* __restrict__ dg1, const float* __restrict__ dbe1,
                const float* __restrict__ dw2, const float* __restrict__ db2,
                const float* __restrict__ dg2, const float* __restrict__ dbe2,
                const float* __restrict__ aw1, const float* __restrict__ ab1,
                const float* __restrict__ ag1, const float* __restrict__ abe1,
                const float* __restrict__ aw2, const float* __restrict__ ab2,
                const float* __restrict__ ag2, const float* __restrict__ abe2,
                const float* __restrict__ lw, const float* __restrict__ lb,
                const float* __restrict__ lg, const float* __restrict__ lbe,
                float* __restrict__ xt_out)       // (B,N,C)
{
    extern __shared__ float sm[];
    float* Wd1 = sm;            // [3][64]
    float* Wd2 = Wd1 + 192;     // [c_in][c_out]
    float* Wa1 = Wd2 + 4096;
    float* Wa2 = Wa1 + 4096;
    float* Wdn = Wa2 + 4096;
    float* Bd1 = Wdn + 4096;
    float* Bd2 = Bd1 + 64;
    float* Ba1 = Bd2 + 64;
    float* Ba2 = Ba1 + 64;
    float* Bdn = Ba2 + 64;

    const int tid = threadIdx.x;

    // Fold BN into weights: W'[o,c] = W[o,c]*g[o]*BN_SC ; b' = b*g*BN_SC + be
    for (int i = tid; i < 4096; i += 256) {
        int c = i >> 6, o = i & 63;
        Wd2[i] = dw2[o * CH + c] * (dg2[o] * BN_SC);
        Wa1[i] = aw1[o * CH + c] * (ag1[o] * BN_SC);
        Wa2[i] = aw2[o * CH + c] * (ag2[o] * BN_SC);
        Wdn[i] = lw[o * CH + c] * (lg[o] * BN_SC);
    }
    for (int i = tid; i < 192; i += 256) {
        int d = i >> 6, o = i & 63;
        Wd1[i] = dw1[o * 3 + d] * (dg1[o] * BN_SC);
    }
    if (tid < 64) {
        Bd1[tid] = db1[tid] * dg1[tid] * BN_SC + dbe1[tid];
        Bd2[tid] = db2[tid] * dg2[tid] * BN_SC + dbe2[tid];
        Ba1[tid] = ab1[tid] * ag1[tid] * BN_SC + abe1[tid];
        Ba2[tid] = ab2[tid] * ag2[tid] * BN_SC + abe2[tid];
        Bdn[tid] = lb[tid] * lg[tid] * BN_SC + lbe[tid];
    }
    __syncthreads();

    const int lane = tid & 31;
    const int half = lane >> 4;
    const int halfOff = half << 5;     // 0 or 32
    const int kk = lane & 15;
    const int gwarp = blockIdx.x * (blockDim.x >> 5) + (tid >> 5);
    const int nwarps = gridDim.x * (blockDim.x >> 5);
    const int npts = NB * NP;

    for (int pt = gwarp; pt < npts; pt += nwarps) {
        int b = pt >> 13;                 // N = 8192
        int n = pt & (NP - 1);
        const float* pb = p + b * 3 * NP;
        int j = idx[(b * NP + n) * KNB + kk];

        // gather own 32 channels of x_t[j] — 8 contiguous float4 loads
        const float4* gxr = (const float4*)(xt_in + ((size_t)(b * NP + j)) * CH + halfOff);
        float4 gxv[8];
#pragma unroll
        for (int q = 0; q < 8; q++) gxv[q] = __ldg(gxr + q);

        float r0 = pb[n] - pb[j];
        float r1 = pb[NP + n] - pb[NP + j];
        float r2 = pb[2 * NP + n] - pb[2 * NP + j];

        // delta layer 1 (3 -> 64), relu — own 32 channels
        float h[32];
#pragma unroll
        for (int i = 0; i < 32; i += 4) {
            float4 w0 = *(const float4*)&Wd1[halfOff + i];
            float4 w1v = *(const float4*)&Wd1[64 + halfOff + i];
            float4 w2v = *(const float4*)&Wd1[128 + halfOff + i];
            float4 bb = *(const float4*)&Bd1[halfOff + i];
            h[i + 0] = fmaxf(bb.x + w0.x * r0 + w1v.x * r1 + w2v.x * r2, 0.f);
            h[i + 1] = fmaxf(bb.y + w0.y * r0 + w1v.y * r1 + w2v.y * r2, 0.f);
            h[i + 2] = fmaxf(bb.z + w0.z * r0 + w1v.z * r1 + w2v.z * r2, 0.f);
            h[i + 3] = fmaxf(bb.w + w0.w * r0 + w1v.w * r1 + w2v.w * r2, 0.f);
        }

        // layer 2: u = Wd2*h + b + gx  (gather folded into acc init)
        unsigned long long acc[16];
#pragma unroll
        for (int q = 0; q < 8; q++) {
            float4 bv = *(const float4*)&Bd2[halfOff + 4 * q];
            acc[2 * q + 0] = pk2(bv.x + gxv[q].x, bv.y + gxv[q].y);
            acc[2 * q + 1] = pk2(bv.z + gxv[q].z, bv.w + gxv[q].w);
        }
        float u[32];
        layer_half<false>(Wd2, halfOff, half, h, acc, u);

        // layer 3: h = relu(Wa1*u + b)
        acc_init_bias_half(Ba1, halfOff, acc);
        layer_half<true>(Wa1, halfOff, half, u, acc, h);

        // layer 4: u = relu(Wa2*h + b)
        acc_init_bias_half(Ba2, halfOff, acc);
        layer_half<true>(Wa2, halfOff, half, h, acc, u);

        // max over k (xor on kk bits stays inside each half-group)
#pragma unroll
        for (int c = 0; c < 32; c++) {
            float v = u[c];
            v = fmaxf(v, __shfl_xor_sync(0xffffffffu, v, 1));
            v = fmaxf(v, __shfl_xor_sync(0xffffffffu, v, 2));
            v = fmaxf(v, __shfl_xor_sync(0xffffffffu, v, 4));
            v = fmaxf(v, __shfl_xor_sync(0xffffffffu, v, 8));
            u[c] = v;
        }

        // down projection: lane computes partials for outputs 4kk..4kk+3
        // over its 32 channels; partner-half partials combined via xor(16).
        float p0 = 0.f, p1 = 0.f, p2 = 0.f, p3 = 0.f;
#pragma unroll
        for (int c = 0; c < 32; c++) {
            float4 w = *(const float4*)&Wdn[(halfOff + c) * CH + 4 * kk];
            p0 += w.x * u[c];
            p1 += w.y * u[c];
            p2 += w.z * u[c];
            p3 += w.w * u[c];
        }
        p0 += __shfl_xor_sync(0xffffffffu, p0, 16);
        p1 += __shfl_xor_sync(0xffffffffu, p1, 16);
        p2 += __shfl_xor_sync(0xffffffffu, p2, 16);
        p3 += __shfl_xor_sync(0xffffffffu, p3, 16);

        if (half == 0) {
            size_t row = ((size_t)(b * NP + n)) * CH;
            float4 res = __ldg((const float4*)(xt_in + row) + kk);
            float4 bb = *(const float4*)&Bdn[4 * kk];
            float4 o;
            o.x = p0 + bb.x + res.x;
            o.y = p1 + bb.y + res.y;
            o.z = p2 + bb.z + res.z;
            o.w = p3 + bb.w + res.w;
            *((float4*)(xt_out + row) + kk) = o;
        }
    }
}

// (B,C,N) -> (B,N,C) tiled transpose
__global__ void transpose_cn_nc(const float* __restrict__ in, float* __restrict__ out) {
    __shared__ float t[32][33];
    int b = blockIdx.z;
    int c0 = blockIdx.y * 32;
    int n0 = blockIdx.x * 32;
    int tx = threadIdx.x, ty = threadIdx.y;
#pragma unroll
    for (int i = ty; i < 32; i += 8)
        t[i][tx] = in[((size_t)b * CH + c0 + i) * NP + n0 + tx];
    __syncthreads();
#pragma unroll
    for (int i = ty; i < 32; i += 8)
        out[((size_t)b * NP + n0 + i) * CH + c0 + tx] = t[tx][i];
}

// (B,N,C) -> (B,C,N) tiled transpose
__global__ void transpose_nc_cn(const float* __restrict__ in, float* __restrict__ out) {
    __shared__ float t[32][33];
    int b = blockIdx.z;
    int n0 = blockIdx.y * 32;
    int c0 = blockIdx.x * 32;
    int tx = threadIdx.x, ty = threadIdx.y;
#pragma unroll
    for (int i = ty; i < 32; i += 8)
        t[i][tx] = in[((size_t)b * NP + n0 + i) * CH + c0 + tx];
    __syncthreads();
#pragma unroll
    for (int i = ty; i < 32; i += 8)
        out[((size_t)b * CH + c0 + i) * NP + n0 + tx] = t[tx][i];
}

extern "C" void kernel_launch(void* const* d_in, const int* in_sizes, int n_in,
                              void* d_out, int out_size) {
    const float* p = (const float*)d_in[0];
    const float* x = (const float*)d_in[1];
    const int* idx = (const int*)d_in[2];
    const float* w[20];
    for (int i = 0; i < 20; i++) w[i] = (const float*)d_in[3 + i];

    float* out = (float*)d_out;
    float* out_x = out + NB * 3 * NP;   // second output tensor

    // pass-through p output
    cudaMemcpyAsync(out, p, (size_t)NB * 3 * NP * sizeof(float),
                    cudaMemcpyDeviceToDevice);

    float *xt0 = nullptr, *xt1 = nullptr;
    cudaGetSymbolAddress((void**)&xt0, g_xt0);
    cudaGetSymbolAddress((void**)&xt1, g_xt1);

    const int SMEM = (192 + 4 * 4096 + 5 * 64) * 4;  // 67584 B
    cudaFuncSetAttribute(pt_block_kernel,
                         cudaFuncAttributeMaxDynamicSharedMemorySize, SMEM);

    dim3 tgrid(NP / 32, CH / 32, NB), tblk(32, 8);
    // transpose input x to (B,N,C)
    transpose_cn_nc<<<tgrid, tblk>>>(x, xt0);

    dim3 grid(296), blk(256);
    const int S_W1 = CH * 3, S_V = CH, S_W = CH * CH;

    // block 0: xt0 -> xt1
    pt_block_kernel<<<grid, blk, SMEM>>>(
        p, xt0, idx,
        w[0], w[1], w[2], w[3],
        w[4], w[5], w[6], w[7],
        w[8], w[9], w[10], w[11],
        w[12], w[13], w[14], w[15],
        w[16], w[17], w[18], w[19],
        xt1);

    // block 1: xt1 -> xt0 (weights at slice index 1)
    pt_block_kernel<<<grid, blk, SMEM>>>(
        p, xt1, idx,
        w[0] + S_W1, w[1] + S_V, w[2] + S_V, w[3] + S_V,
        w[4] + S_W, w[5] + S_V, w[6] + S_V, w[7] + S_V,
        w[8] + S_W, w[9] + S_V, w[10] + S_V, w[11] + S_V,
        w[12] + S_W, w[13] + S_V, w[14] + S_V, w[15] + S_V,
        w[16] + S_W, w[17] + S_V, w[18] + S_V, w[19] + S_V,
        xt0);

    // un-transpose to (B,C,N) output
    dim3 tgrid2(CH / 32, NP / 32, NB);
    transpose_nc_cn<<<tgrid2, tblk>>>(xt0, out_x);
}

// round 9
// speedup vs baseline: 1.2351x; 1.2351x over previous
#include <cuda_runtime.h>
#include <cstdint>

#define NB 4
#define NP 8192
#define CH 64
#define KNB 16
// 1/sqrt(1 + 1e-5)
#define BN_SC 0.9999950000374997f

// scratch (static device arrays — no allocation)
__device__ __align__(16) float g_xt0[NB * NP * CH];   // x_t (B,N,C)
__device__ __align__(16) float g_xt1[NB * NP * CH];
__device__ __align__(16) float g_y[NB * NP * CH];     // y = W3·x, (B,N,C)
__device__ __align__(16) float g_wc[CH * CH];         // Wc^T  [c_in][c_out]
__device__ __align__(16) float g_bc[CH];

__device__ __forceinline__ unsigned long long pk2(float x, float y) {
    unsigned long long r;
    asm("mov.b64 %0, {%1, %2};" : "=l"(r) : "f"(x), "f"(y));
    return r;
}
__device__ __forceinline__ void fma2(unsigned long long& d, unsigned long long a, unsigned long long b) {
    asm("fma.rn.f32x2 %0, %1, %2, %0;" : "+l"(d) : "l"(a), "l"(b));
}
__device__ __forceinline__ void upk2(unsigned long long v, float& x, float& y) {
    asm("mov.b64 {%0, %1}, %2;" : "=f"(x), "=f"(y) : "l"(v));
}

// One 32-output pass of a 64->64 layer. Wt layout [c_in][c_out] in SMEM
// (warp-uniform LDS.128 broadcast). acc[16] pre-initialized. Reads all 64
// inputs from registers; writes out[0:32] with optional relu.
template <bool RELU>
__device__ __forceinline__ void pass32(const float* __restrict__ Wt, int off,
                                       const float* in,
                                       unsigned long long* acc, float* out) {
#pragma unroll
    for (int c = 0; c < CH; c++) {
        unsigned long long v2 = pk2(in[c], in[c]);
        const ulonglong2* wr = reinterpret_cast<const ulonglong2*>(Wt + c * CH + off);
#pragma unroll
        for (int q = 0; q < 8; q++) {
            ulonglong2 w = wr[q];
            fma2(acc[2 * q + 0], w.x, v2);
            fma2(acc[2 * q + 1], w.y, v2);
        }
    }
#pragma unroll
    for (int q = 0; q < 16; q++) {
        float x, y;
        upk2(acc[q], x, y);
        out[2 * q + 0] = RELU ? fmaxf(x, 0.f) : x;
        out[2 * q + 1] = RELU ? fmaxf(y, 0.f) : y;
    }
}

// ---------------- prep kernels (per pt-block) ----------------

// Wc^T = (W3·W2)^T and bc = W3·b2 + b3f, all BN-folded.
__global__ void prep_wc(const float* __restrict__ aw1, const float* __restrict__ ag1,
                        const float* __restrict__ ab1, const float* __restrict__ abe1,
                        const float* __restrict__ dw2, const float* __restrict__ dg2,
                        const float* __restrict__ db2, const float* __restrict__ dbe2) {
    __shared__ float A[CH * CH];   // W3f [o][m]
    __shared__ float Bm[CH * CH];  // W2f [m][c]
    __shared__ float b2s[CH];
    int tid = threadIdx.x;
    for (int i = tid; i < CH * CH; i += 256) {
        int o = i >> 6, m = i & 63;
        A[i] = aw1[o * CH + m] * (ag1[o] * BN_SC);
        Bm[i] = dw2[o * CH + m] * (dg2[o] * BN_SC);  // row index plays role of m
    }
    if (tid < CH) b2s[tid] = db2[tid] * dg2[tid] * BN_SC + dbe2[tid];
    __syncthreads();
    int o = tid & 63, seg = tid >> 6;
    for (int c = seg * 16; c < seg * 16 + 16; c++) {
        float acc = 0.f;
#pragma unroll 8
        for (int m = 0; m < CH; m++) acc += A[o * CH + m] * Bm[m * CH + c];
        g_wc[c * CH + o] = acc;
    }
    if (seg == 0) {
        float acc = ab1[o] * ag1[o] * BN_SC + abe1[o];
        for (int m = 0; m < CH; m++) acc += A[o * CH + m] * b2s[m];
        g_bc[o] = acc;
    }
}

// y_t[n] = W3f · x_t[n]. One lane per point, two 32-out passes.
// MUST be launched with grid*blk/32*32 >= NB*NP points: grid = 128, blk = 256.
__global__ void __launch_bounds__(256, 2)
prep_y(const float* __restrict__ xt,
       const float* __restrict__ aw1, const float* __restrict__ ag1,
       float* __restrict__ yt) {
    __shared__ float W3t[CH * CH];  // [c][o]
    int tid = threadIdx.x;
    for (int i = tid; i < CH * CH; i += 256) {
        int c = i >> 6, o = i & 63;
        W3t[i] = aw1[o * CH + c] * (ag1[o] * BN_SC);
    }
    __syncthreads();

    int lane = tid & 31;
    int gwarp = blockIdx.x * 8 + (tid >> 5);
    int pt = gwarp * 32 + lane;
    if (pt >= NB * NP) return;

    float in[CH];
    const float4* xr = (const float4*)(xt + (size_t)pt * CH);
#pragma unroll
    for (int q = 0; q < 16; q++) {
        float4 v = __ldg(xr + q);
        in[4 * q] = v.x; in[4 * q + 1] = v.y; in[4 * q + 2] = v.z; in[4 * q + 3] = v.w;
    }
    float out[32];
    unsigned long long acc[16];
    float4* yr = (float4*)(yt + (size_t)pt * CH);
#pragma unroll
    for (int halfo = 0; halfo < 2; halfo++) {
#pragma unroll
        for (int q = 0; q < 16; q++) acc[q] = 0ull;
        pass32<false>(W3t, halfo * 32, in, acc, out);
#pragma unroll
        for (int q = 0; q < 8; q++) {
            float4 v;
            v.x = out[4 * q]; v.y = out[4 * q + 1]; v.z = out[4 * q + 2]; v.w = out[4 * q + 3];
            yr[halfo * 8 + q] = v;
        }
    }
}

// ---------------- main block kernel ----------------
// Per-column hot loop: delta1 (3->64) -> layerC (Wc·h + y[j] + bc, relu)
// -> layer4 (W4, relu) -> kmax -> down + residual.
// Warp layout: lane = half*16 + kk; warp = 2 points x 16 neighbors.
__global__ void __launch_bounds__(256, 1)
pt_block_kernel(const float* __restrict__ p,      // (B,3,N)
                const float* __restrict__ xt_in,  // (B,N,C)
                const float* __restrict__ y_t,    // (B,N,C)
                const int* __restrict__ idx,      // (B,N,K)
                const float* __restrict__ dw1, const float* __restrict__ db1,
                const float* __restrict__ dg1, const float* __restrict__ dbe1,
                const float* __restrict__ aw2, const float* __restrict__ ab2,
                const float* __restrict__ ag2, const float* __restrict__ abe2,
                const float* __restrict__ lw, const float* __restrict__ lb,
                const float* __restrict__ lg, const float* __restrict__ lbe,
                float* __restrict__ xt_out)       // (B,N,C)
{
    extern __shared__ float sm[];
    float* Wd1 = sm;            // [3][64]
    float* WcS = Wd1 + 192;     // [c][o]
    float* W4S = WcS + 4096;
    float* WdnS = W4S + 4096;
    float* Bd1 = WdnS + 4096;
    float* Bc = Bd1 + 64;
    float* B4 = Bc + 64;
    float* Bdn = B4 + 64;

    const int tid = threadIdx.x;

    for (int i = tid; i < 4096; i += 256) {
        int c = i >> 6, o = i & 63;
        WcS[i] = g_wc[i];                               // precomputed, folded
        W4S[i] = aw2[o * CH + c] * (ag2[o] * BN_SC);
        WdnS[i] = lw[o * CH + c] * (lg[o] * BN_SC);
    }
    for (int i = tid; i < 192; i += 256) {
        int d = i >> 6, o = i & 63;
        Wd1[i] = dw1[o * 3 + d] * (dg1[o] * BN_SC);
    }
    if (tid < 64) {
        Bd1[tid] = db1[tid] * dg1[tid] * BN_SC + dbe1[tid];
        Bc[tid] = g_bc[tid];
        B4[tid] = ab2[tid] * ag2[tid] * BN_SC + abe2[tid];
        Bdn[tid] = lb[tid] * lg[tid] * BN_SC + lbe[tid];
    }
    __syncthreads();

    const int lane = tid & 31;
    const int half = lane >> 4;
    const int kk = lane & 15;
    const int gwarp = blockIdx.x * (blockDim.x >> 5) + (tid >> 5);
    const int nwarps = gridDim.x * (blockDim.x >> 5);
    const int npairs = NB * NP / 2;

    for (int pair = gwarp; pair < npairs; pair += nwarps) {
        int bn = pair * 2;
        int b = bn >> 13;                 // N = 8192
        int n = (bn & (NP - 1)) + half;
        const float* pb = p + b * 3 * NP;
        int j = idx[(b * NP + n) * KNB + kk];

        const float4* yrow = (const float4*)(y_t + ((size_t)(b * NP + j)) * CH);
        float4 yv[8];
#pragma unroll
        for (int q = 0; q < 8; q++) yv[q] = __ldg(yrow + q);   // y lo-half

        float r0 = pb[n] - pb[j];
        float r1 = pb[NP + n] - pb[NP + j];
        float r2 = pb[2 * NP + n] - pb[2 * NP + j];

        // delta layer 1 (3 -> 64), relu
        float h[CH];
#pragma unroll
        for (int co = 0; co < CH; co += 4) {
            float4 w0 = *(const float4*)&Wd1[co];
            float4 w1v = *(const float4*)&Wd1[64 + co];
            float4 w2v = *(const float4*)&Wd1[128 + co];
            float4 bb = *(const float4*)&Bd1[co];
            h[co + 0] = fmaxf(bb.x + w0.x * r0 + w1v.x * r1 + w2v.x * r2, 0.f);
            h[co + 1] = fmaxf(bb.y + w0.y * r0 + w1v.y * r1 + w2v.y * r2, 0.f);
            h[co + 2] = fmaxf(bb.z + w0.z * r0 + w1v.z * r1 + w2v.z * r2, 0.f);
            h[co + 3] = fmaxf(bb.w + w0.w * r0 + w1v.w * r1 + w2v.w * r2, 0.f);
        }

        // layer C: u = relu(Wc·h + y[j] + bc)
        float u[CH];
        unsigned long long acc[16];
#pragma unroll
        for (int q = 0; q < 8; q++) {
            float4 bv = *(const float4*)&Bc[4 * q];
            acc[2 * q + 0] = pk2(bv.x + yv[q].x, bv.y + yv[q].y);
            acc[2 * q + 1] = pk2(bv.z + yv[q].z, bv.w + yv[q].w);
        }
#pragma unroll
        for (int q = 0; q < 8; q++) yv[q] = __ldg(yrow + 8 + q);  // y hi-half
        pass32<true>(WcS, 0, h, acc, u);
#pragma unroll
        for (int q = 0; q < 8; q++) {
            float4 bv = *(const float4*)&Bc[32 + 4 * q];
            acc[2 * q + 0] = pk2(bv.x + yv[q].x, bv.y + yv[q].y);
            acc[2 * q + 1] = pk2(bv.z + yv[q].z, bv.w + yv[q].w);
        }
        pass32<true>(WcS, 32, h, acc, u + 32);

        // layer 4: h = relu(W4·u + b4)
#pragma unroll
        for (int q = 0; q < 8; q++) {
            float4 bv = *(const float4*)&B4[4 * q];
            acc[2 * q + 0] = pk2(bv.x, bv.y);
            acc[2 * q + 1] = pk2(bv.z, bv.w);
        }
        pass32<true>(W4S, 0, u, acc, h);
#pragma unroll
        for (int q = 0; q < 8; q++) {
            float4 bv = *(const float4*)&B4[32 + 4 * q];
            acc[2 * q + 0] = pk2(bv.x, bv.y);
            acc[2 * q + 1] = pk2(bv.z, bv.w);
        }
        pass32<true>(W4S, 32, u, acc, h + 32);

        // max over k (16 lanes per point)
#pragma unroll
        for (int c = 0; c < CH; c++) {
            float v = h[c];
            v = fmaxf(v, __shfl_xor_sync(0xffffffffu, v, 1));
            v = fmaxf(v, __shfl_xor_sync(0xffffffffu, v, 2));
            v = fmaxf(v, __shfl_xor_sync(0xffffffffu, v, 4));
            v = fmaxf(v, __shfl_xor_sync(0xffffffffu, v, 8));
            h[c] = v;
        }

        // down projection: lane kk computes outputs 4*kk .. 4*kk+3
        float4 ob = *(const float4*)&Bdn[4 * kk];
        float o0 = ob.x, o1 = ob.y, o2 = ob.z, o3 = ob.w;
#pragma unroll
        for (int c = 0; c < CH; c++) {
            float4 w = *(const float4*)&WdnS[c * CH + 4 * kk];
            o0 += w.x * h[c];
            o1 += w.y * h[c];
            o2 += w.z * h[c];
            o3 += w.w * h[c];
        }
        size_t row = ((size_t)(b * NP + n)) * CH;
        float4 res = __ldg((const float4*)(xt_in + row) + kk);
        float4 o;
        o.x = o0 + res.x; o.y = o1 + res.y; o.z = o2 + res.z; o.w = o3 + res.w;
        *((float4*)(xt_out + row) + kk) = o;
    }
}

// (B,C,N) -> (B,N,C) tiled transpose
__global__ void transpose_cn_nc(const float* __restrict__ in, float* __restrict__ out) {
    __shared__ float t[32][33];
    int b = blockIdx.z;
    int c0 = blockIdx.y * 32;
    int n0 = blockIdx.x * 32;
    int tx = threadIdx.x, ty = threadIdx.y;
#pragma unroll
    for (int i = ty; i < 32; i += 8)
        t[i][tx] = in[((size_t)b * CH + c0 + i) * NP + n0 + tx];
    __syncthreads();
#pragma unroll
    for (int i = ty; i < 32; i += 8)
        out[((size_t)b * NP + n0 + i) * CH + c0 + tx] = t[tx][i];
}

// (B,N,C) -> (B,C,N) tiled transpose
__global__ void transpose_nc_cn(const float* __restrict__ in, float* __restrict__ out) {
    __shared__ float t[32][33];
    int b = blockIdx.z;
    int n0 = blockIdx.y * 32;
    int c0 = blockIdx.x * 32;
    int tx = threadIdx.x, ty = threadIdx.y;
#pragma unroll
    for (int i = ty; i < 32; i += 8)
        t[i][tx] = in[((size_t)b * NP + n0 + i) * CH + c0 + tx];
    __syncthreads();
#pragma unroll
    for (int i = ty; i < 32; i += 8)
        out[((size_t)b * CH + c0 + i) * NP + n0 + tx] = t[tx][i];
}

extern "C" void kernel_launch(void* const* d_in, const int* in_sizes, int n_in,
                              void* d_out, int out_size) {
    const float* p = (const float*)d_in[0];
    const float* x = (const float*)d_in[1];
    const int* idx = (const int*)d_in[2];
    const float* w[20];
    for (int i = 0; i < 20; i++) w[i] = (const float*)d_in[3 + i];

    float* out = (float*)d_out;
    float* out_x = out + NB * 3 * NP;   // second output tensor

    cudaMemcpyAsync(out, p, (size_t)NB * 3 * NP * sizeof(float),
                    cudaMemcpyDeviceToDevice);

    float *xt0, *xt1, *yb;
    cudaGetSymbolAddress((void**)&xt0, g_xt0);
    cudaGetSymbolAddress((void**)&xt1, g_xt1);
    cudaGetSymbolAddress((void**)&yb, g_y);

    const int SMEM = (192 + 3 * 4096 + 4 * 64) * 4;  // 50944 B
    cudaFuncSetAttribute(pt_block_kernel,
                         cudaFuncAttributeMaxDynamicSharedMemorySize, SMEM);

    dim3 tgrid(NP / 32, CH / 32, NB), tblk(32, 8);
    transpose_cn_nc<<<tgrid, tblk>>>(x, xt0);

    dim3 grid(296), blk(256);
    const int S_W1 = CH * 3, S_V = CH, S_W = CH * CH;

    for (int blkI = 0; blkI < 2; blkI++) {
        const float* dw1 = w[0] + blkI * S_W1;
        const float* db1 = w[1] + blkI * S_V;
        const float* dg1 = w[2] + blkI * S_V;
        const float* dbe1 = w[3] + blkI * S_V;
        const float* dw2 = w[4] + blkI * S_W;
        const float* db2 = w[5] + blkI * S_V;
        const float* dg2 = w[6] + blkI * S_V;
        const float* dbe2 = w[7] + blkI * S_V;
        const float* aw1 = w[8] + blkI * S_W;
        const float* ab1 = w[9] + blkI * S_V;
        const float* ag1 = w[10] + blkI * S_V;
        const float* abe1 = w[11] + blkI * S_V;
        const float* aw2 = w[12] + blkI * S_W;
        const float* ab2 = w[13] + blkI * S_V;
        const float* ag2 = w[14] + blkI * S_V;
        const float* abe2 = w[15] + blkI * S_V;
        const float* lw = w[16] + blkI * S_W;
        const float* lb = w[17] + blkI * S_V;
        const float* lg = w[18] + blkI * S_V;
        const float* lbe = w[19] + blkI * S_V;

        const float* xin = blkI == 0 ? xt0 : xt1;
        float* xout = blkI == 0 ? xt1 : xt0;

        prep_wc<<<1, 256>>>(aw1, ag1, ab1, abe1, dw2, dg2, db2, dbe2);
        // 32768 points / (8 warps * 32 lanes) = 128 blocks   (FIX: was 16)
        prep_y<<<128, 256>>>(xin, aw1, ag1, yb);
        pt_block_kernel<<<grid, blk, SMEM>>>(
            p, xin, yb, idx,
            dw1, db1, dg1, dbe1,
            aw2, ab2, ag2, abe2,
            lw, lb, lg, lbe,
            xout);
    }

    dim3 tgrid2(CH / 32, NP / 32, NB);
    transpose_nc_cn<<<tgrid2, tblk>>>(xt0, out_x);
}